// round 1
// baseline (speedup 1.0000x reference)
#include <cuda_runtime.h>

#define NN     4096
#define DD     256
#define TWO_N  8192
#define INV_T  2.0f          // 1 / 0.5 temperature
#define BM     128
#define BN     128
#define BK     8
#define NTILES 64            // TWO_N / BN

// scratch: partial (max, sumexp) per (row, column-tile); per-row value
__device__ float g_pm[TWO_N * NTILES];
__device__ float g_ps[TWO_N * NTILES];
__device__ float g_rowv[TWO_N];

__device__ __forceinline__ const float* zrow(const float* zi, const float* zj, int r) {
    return (r < NN) ? (zi + (long)r * DD) : (zj + (long)(r - NN) * DD);
}

// One 128x128 tile of sim = (z z^T)/T, upper triangle of tile grid only.
// Emits streaming-softmax partials for its rows (slot bc) and, for off-diagonal
// tiles, also for its columns (slot br) — the symmetric contribution.
__global__ __launch_bounds__(256, 2)
void tile_kernel(const float* __restrict__ zi, const float* __restrict__ zj) {
    const int br = blockIdx.y, bc = blockIdx.x;
    if (bc < br) return;

    __shared__ float As[BK][BM + 4];
    __shared__ float Bs[BK][BN + 4];
    __shared__ float colbuf[16][BN];
    __shared__ float colmax[BN];

    const int tid = threadIdx.x;
    const int tx = tid & 15, ty = tid >> 4;
    const int gr0 = br * BM, gc0 = bc * BN;
    const float* Ab = zrow(zi, zj, gr0);
    const float* Bb = zrow(zi, zj, gc0);

    float acc[8][8];
#pragma unroll
    for (int i = 0; i < 8; i++)
#pragma unroll
        for (int j = 0; j < 8; j++) acc[i][j] = 0.f;

    // loader: 1 float4 per thread per operand per k-chunk
    const int lrow = tid >> 1;
    const int lk   = (tid & 1) * 4;
    const float* Ap = Ab + lrow * DD + lk;
    const float* Bp = Bb + lrow * DD + lk;

    for (int kk = 0; kk < DD; kk += BK) {
        float4 av = *(const float4*)(Ap + kk);
        float4 bv = *(const float4*)(Bp + kk);
        __syncthreads();
        As[lk + 0][lrow] = av.x; As[lk + 1][lrow] = av.y;
        As[lk + 2][lrow] = av.z; As[lk + 3][lrow] = av.w;
        Bs[lk + 0][lrow] = bv.x; Bs[lk + 1][lrow] = bv.y;
        Bs[lk + 2][lrow] = bv.z; Bs[lk + 3][lrow] = bv.w;
        __syncthreads();
#pragma unroll
        for (int k = 0; k < BK; k++) {
            float a[8], b[8];
            *(float4*)&a[0] = *(const float4*)&As[k][ty * 8];
            *(float4*)&a[4] = *(const float4*)&As[k][ty * 8 + 4];
            *(float4*)&b[0] = *(const float4*)&Bs[k][tx * 8];
            *(float4*)&b[4] = *(const float4*)&Bs[k][tx * 8 + 4];
#pragma unroll
            for (int i = 0; i < 8; i++)
#pragma unroll
                for (int j = 0; j < 8; j++)
                    acc[i][j] = fmaf(a[i], b[j], acc[i][j]);
        }
    }

    // scale by 1/T; mask diagonal (only possible when br == bc)
#pragma unroll
    for (int i = 0; i < 8; i++)
#pragma unroll
        for (int j = 0; j < 8; j++) acc[i][j] *= INV_T;
    if (br == bc) {
#pragma unroll
        for (int i = 0; i < 8; i++)
#pragma unroll
            for (int j = 0; j < 8; j++)
                if (ty * 8 + i == tx * 8 + j) acc[i][j] = -3.0e38f;
    }

    // ---- row partials: reduce across tx (16-lane shfl groups) ----
#pragma unroll
    for (int i = 0; i < 8; i++) {
        float m = acc[i][0];
#pragma unroll
        for (int j = 1; j < 8; j++) m = fmaxf(m, acc[i][j]);
#pragma unroll
        for (int off = 8; off >= 1; off >>= 1)
            m = fmaxf(m, __shfl_xor_sync(0xffffffffu, m, off));
        float s = 0.f;
#pragma unroll
        for (int j = 0; j < 8; j++) s += __expf(acc[i][j] - m);
#pragma unroll
        for (int off = 8; off >= 1; off >>= 1)
            s += __shfl_xor_sync(0xffffffffu, s, off);
        if (tx == 0) {
            const int gr = gr0 + ty * 8 + i;
            g_pm[gr * NTILES + bc] = m;
            g_ps[gr * NTILES + bc] = s;
        }
    }

    if (br == bc) return;   // diagonal tile contributes once only

    // ---- column partials (symmetric contribution), via smem transpose ----
#pragma unroll
    for (int j = 0; j < 8; j++) {
        float m = acc[0][j];
#pragma unroll
        for (int i = 1; i < 8; i++) m = fmaxf(m, acc[i][j]);
        colbuf[ty][tx * 8 + j] = m;
    }
    __syncthreads();
    if (tid < BN) {
        float m = colbuf[0][tid];
#pragma unroll
        for (int t = 1; t < 16; t++) m = fmaxf(m, colbuf[t][tid]);
        colmax[tid] = m;
    }
    __syncthreads();
    float cm[8];
#pragma unroll
    for (int j = 0; j < 8; j++) cm[j] = colmax[tx * 8 + j];
#pragma unroll
    for (int j = 0; j < 8; j++) {
        float s = 0.f;
#pragma unroll
        for (int i = 0; i < 8; i++) s += __expf(acc[i][j] - cm[j]);
        colbuf[ty][tx * 8 + j] = s;
    }
    __syncthreads();
    if (tid < BN) {
        float s = 0.f;
#pragma unroll
        for (int t = 0; t < 16; t++) s += colbuf[t][tid];
        const int gc = gc0 + tid;
        g_pm[gc * NTILES + br] = colmax[tid];
        g_ps[gc * NTILES + br] = s;
    }
}

// One warp per row: merge 64 (m,s) partials -> lse, compute positive-pair dot,
// write per-row value (lse - pos_sim).
__global__ void finalize_kernel(const float* __restrict__ zi, const float* __restrict__ zj) {
    const int warp = (blockIdx.x * blockDim.x + threadIdx.x) >> 5;
    const int lane = threadIdx.x & 31;
    if (warp >= TWO_N) return;
    const int r = warp;

    const float m0 = g_pm[r * NTILES + lane];
    const float m1 = g_pm[r * NTILES + 32 + lane];
    const float s0 = g_ps[r * NTILES + lane];
    const float s1 = g_ps[r * NTILES + 32 + lane];
    float m = fmaxf(m0, m1);
#pragma unroll
    for (int off = 16; off >= 1; off >>= 1)
        m = fmaxf(m, __shfl_xor_sync(0xffffffffu, m, off));
    float S = s0 * __expf(m0 - m) + s1 * __expf(m1 - m);
#pragma unroll
    for (int off = 16; off >= 1; off >>= 1)
        S += __shfl_xor_sync(0xffffffffu, S, off);

    const int p = (r < NN) ? r + NN : r - NN;
    const float* a = zrow(zi, zj, r);
    const float* b = zrow(zi, zj, p);
    float dot = 0.f;
#pragma unroll
    for (int q = 0; q < 2; q++) {
        const int k = lane * 8 + q * 4;
        float4 x = *(const float4*)(a + k);
        float4 y = *(const float4*)(b + k);
        dot += x.x * y.x + x.y * y.y + x.z * y.z + x.w * y.w;
    }
#pragma unroll
    for (int off = 16; off >= 1; off >>= 1)
        dot += __shfl_xor_sync(0xffffffffu, dot, off);

    if (lane == 0)
        g_rowv[r] = (m + __logf(S)) - dot * INV_T;
}

__global__ void reduce_kernel(float* __restrict__ out) {
    __shared__ float sm[8];
    float s = 0.f;
    for (int i = threadIdx.x; i < TWO_N; i += 256) s += g_rowv[i];
#pragma unroll
    for (int off = 16; off >= 1; off >>= 1)
        s += __shfl_xor_sync(0xffffffffu, s, off);
    if ((threadIdx.x & 31) == 0) sm[threadIdx.x >> 5] = s;
    __syncthreads();
    if (threadIdx.x < 8) {
        s = sm[threadIdx.x];
#pragma unroll
        for (int off = 4; off >= 1; off >>= 1)
            s += __shfl_xor_sync(0x000000ffu, s, off);
        if (threadIdx.x == 0) out[0] = s / (float)TWO_N;
    }
}

extern "C" void kernel_launch(void* const* d_in, const int* in_sizes, int n_in,
                              void* d_out, int out_size) {
    const float* zi = (const float*)d_in[0];
    const float* zj = (const float*)d_in[1];
    float* out = (float*)d_out;

    dim3 grid1(NTILES, NTILES);
    tile_kernel<<<grid1, 256>>>(zi, zj);
    finalize_kernel<<<(TWO_N * 32) / 256, 256>>>(zi, zj);
    reduce_kernel<<<1, 256>>>(out);
}

// round 6
// speedup vs baseline: 1.3924x; 1.3924x over previous
#include <cuda_runtime.h>
#include <cuda_bf16.h>
#include <cstdint>

#define NN      4096
#define DD      256
#define TWO_N   8192
#define NTILES  64
#define BMN     128
#define KC      64          // K-chunk (bf16 elems) -> 128B rows, SW128-style swizzle
#define NCHUNK  4           // DD / KC
#define SCALE2  2.8853900817779268f   // (1/T) * log2(e) = 2 * 1.44269504
#define LN2F    0.6931471805599453f

#define TILE_BYTES 16384                 // 128 rows x 64 bf16 x 2B
#define DYN_BYTES  (4 * TILE_BYTES + 1024)  // Ahi, Alo, Bhi, Blo (single-buffered)

// scratch partials (base-2 domain): (m2, sum 2^(x2-m2)) per (row, tile-slot)
__device__ float g_pm[TWO_N * NTILES];
__device__ float g_ps[TWO_N * NTILES];
__device__ float g_rowv[TWO_N];

// ---------------- helpers (portable PTX only: ldmatrix + mma.sync) ----------
__device__ __forceinline__ uint32_t smem_u32(const void* p) {
    uint32_t a;
    asm("{ .reg .u64 t; cvta.to.shared.u64 t, %1; cvt.u32.u64 %0, t; }" : "=r"(a) : "l"(p));
    return a;
}
#define SWZ(o) ((o) ^ (((o) >> 3) & 0x70))
#define STS128(a, r0, r1, r2, r3) \
    asm volatile("st.shared.v4.b32 [%0], {%1,%2,%3,%4};" :: "r"(a), "r"(r0), "r"(r1), "r"(r2), "r"(r3) : "memory")
#define LDM_X4(r, a) \
    asm volatile("ldmatrix.sync.aligned.m8n8.x4.shared.b16 {%0,%1,%2,%3}, [%4];" \
        : "=r"((r)[0]), "=r"((r)[1]), "=r"((r)[2]), "=r"((r)[3]) : "r"(a))
#define LDM_X2(r, a) \
    asm volatile("ldmatrix.sync.aligned.m8n8.x2.shared.b16 {%0,%1}, [%2];" \
        : "=r"((r)[0]), "=r"((r)[1]) : "r"(a))
#define MMA16816(c, a, b) \
    asm volatile("mma.sync.aligned.m16n8k16.row.col.f32.bf16.bf16.f32 " \
        "{%0,%1,%2,%3}, {%4,%5,%6,%7}, {%8,%9}, {%0,%1,%2,%3};" \
        : "+f"((c)[0]), "+f"((c)[1]), "+f"((c)[2]), "+f"((c)[3]) \
        : "r"((a)[0]), "r"((a)[1]), "r"((a)[2]), "r"((a)[3]), "r"((b)[0]), "r"((b)[1]))

__device__ __forceinline__ const float* zrow(const float* zi, const float* zj, int r) {
    return (r < NN) ? (zi + (long)r * DD) : (zj + (long)(r - NN) * DD);
}

// exp2 for u <= 0, FMA-pipe only (no MUFU). ~3e-5 rel err; tiny u underflows to ~0.
__device__ __forceinline__ float exp2_poly(float u) {
    u = fmaxf(u, -126.0f);
    float n = floorf(u);
    float f = u - n;
    float p = fmaf(f, 0.000154035304f, 0.00133335581f);
    p = fmaf(p, f, 0.00961812911f);
    p = fmaf(p, f, 0.0555041087f);
    p = fmaf(p, f, 0.240226507f);
    p = fmaf(p, f, 0.693147181f);
    p = fmaf(p, f, 1.0f);
    return __int_as_float(((int)n + 127) << 23) * p;
}

// load a 32-float slice of one row, split into hi/lo bf16, store swizzled
__device__ __forceinline__ void load_half_row_split(uint32_t hi_tile, uint32_t lo_tile,
                                                    const float* src, int row, int bytecol0) {
#pragma unroll
    for (int g = 0; g < 4; g++) {
        float4 a = *(const float4*)(src + g * 8);
        float4 b = *(const float4*)(src + g * 8 + 4);
        __nv_bfloat16 h0 = __float2bfloat16_rn(a.x), h1 = __float2bfloat16_rn(a.y);
        __nv_bfloat16 h2 = __float2bfloat16_rn(a.z), h3 = __float2bfloat16_rn(a.w);
        __nv_bfloat16 h4 = __float2bfloat16_rn(b.x), h5 = __float2bfloat16_rn(b.y);
        __nv_bfloat16 h6 = __float2bfloat16_rn(b.z), h7 = __float2bfloat16_rn(b.w);
        __nv_bfloat162 hp0 = __halves2bfloat162(h0, h1), hp1 = __halves2bfloat162(h2, h3);
        __nv_bfloat162 hp2 = __halves2bfloat162(h4, h5), hp3 = __halves2bfloat162(h6, h7);
        __nv_bfloat162 lp0 = __floats2bfloat162_rn(a.x - __bfloat162float(h0), a.y - __bfloat162float(h1));
        __nv_bfloat162 lp1 = __floats2bfloat162_rn(a.z - __bfloat162float(h2), a.w - __bfloat162float(h3));
        __nv_bfloat162 lp2 = __floats2bfloat162_rn(b.x - __bfloat162float(h4), b.y - __bfloat162float(h5));
        __nv_bfloat162 lp3 = __floats2bfloat162_rn(b.z - __bfloat162float(h6), b.w - __bfloat162float(h7));
        uint32_t o = (uint32_t)row * 128u + (uint32_t)(bytecol0 + g * 16);
        uint32_t sw = SWZ(o);
        STS128(hi_tile + sw, *(uint32_t*)&hp0, *(uint32_t*)&hp1, *(uint32_t*)&hp2, *(uint32_t*)&hp3);
        STS128(lo_tile + sw, *(uint32_t*)&lp0, *(uint32_t*)&lp1, *(uint32_t*)&lp2, *(uint32_t*)&lp3);
    }
}

__global__ __launch_bounds__(256)
void tile_kernel(const float* __restrict__ zi, const float* __restrict__ zj) {
    const int br = blockIdx.y, bc = blockIdx.x;
    if (bc < br) return;

    extern __shared__ char dynsmem[];
    __shared__ float s_row[BMN][4];   // row partial sums per warp_n
    __shared__ float s_col[BMN][2];   // col partial sums per warp_m
    __shared__ float s_red[8];

    const int tid  = threadIdx.x;
    const int wid  = tid >> 5;
    const int lane = tid & 31;
    const int wm   = (wid >> 2) * 64;   // warp row offset (warp_m in {0,1})
    const int wn   = (wid & 3) * 32;    // warp col offset (warp_n in {0..3})

    const uint32_t dynbase = (smem_u32(dynsmem) + 1023u) & ~1023u;
    const uint32_t Ahi = dynbase;
    const uint32_t Alo = dynbase + TILE_BYTES;
    const uint32_t Bhi = dynbase + 2 * TILE_BYTES;
    const uint32_t Blo = dynbase + 3 * TILE_BYTES;

    // per-lane ldmatrix constants (SW128 xor mask is constant per lane)
    const int rA  = lane & 15;
    const uint32_t kbA  = (uint32_t)((lane >> 4) * 16);
    const uint32_t xorA = (uint32_t)((rA & 7) << 4);
    const int rB  = lane & 7;
    const uint32_t kbB  = (uint32_t)(((lane >> 3) & 1) * 16);
    const uint32_t xorB = (uint32_t)(rB << 4);
    uint32_t ArowB[4], BrowB[4];
#pragma unroll
    for (int mi = 0; mi < 4; mi++) ArowB[mi] = (uint32_t)((wm + mi * 16 + rA) * 128);
#pragma unroll
    for (int ni = 0; ni < 4; ni++) BrowB[ni] = (uint32_t)((wn + ni * 8 + rB) * 128);

    float acc[4][4][4];
#pragma unroll
    for (int mi = 0; mi < 4; mi++)
#pragma unroll
        for (int ni = 0; ni < 4; ni++)
#pragma unroll
            for (int q = 0; q < 4; q++) acc[mi][ni][q] = 0.f;

    // loader assignment: each thread stages half a row (32 floats) per operand
    const int lrow = tid >> 1;
    const int lcol = (tid & 1) * 32;          // float index
    const int lbyte = lcol * 2;               // byte col in bf16 tile
    const float* Ap = zrow(zi, zj, br * BMN) + lrow * DD + lcol;
    const float* Bp = zrow(zi, zj, bc * BMN) + lrow * DD + lcol;

#pragma unroll 1
    for (int c = 0; c < NCHUNK; c++) {
        __syncthreads();   // previous chunk's MMAs done reading smem
        load_half_row_split(Ahi, Alo, Ap + c * KC, lrow, lbyte);
        load_half_row_split(Bhi, Blo, Bp + c * KC, lrow, lbyte);
        __syncthreads();

#pragma unroll
        for (int ks = 0; ks < 4; ks++) {
            const uint32_t kA = ((uint32_t)(ks * 32) + kbA) ^ xorA;
            const uint32_t kB = ((uint32_t)(ks * 32) + kbB) ^ xorB;
            uint32_t ah[4][4], al[4][4], bh[4][2], bl[4][2];
#pragma unroll
            for (int mi = 0; mi < 4; mi++) {
                const uint32_t off = ArowB[mi] + kA;
                LDM_X4(ah[mi], Ahi + off);
                LDM_X4(al[mi], Alo + off);
            }
#pragma unroll
            for (int ni = 0; ni < 4; ni++) {
                const uint32_t off = BrowB[ni] + kB;
                LDM_X2(bh[ni], Bhi + off);
                LDM_X2(bl[ni], Blo + off);
            }
#pragma unroll
            for (int mi = 0; mi < 4; mi++)
#pragma unroll
                for (int ni = 0; ni < 4; ni++) {
                    MMA16816(acc[mi][ni], ah[mi], bh[ni]);
                    MMA16816(acc[mi][ni], ah[mi], bl[ni]);
                    MMA16816(acc[mi][ni], al[mi], bh[ni]);
                }
        }
    }

    // ---- epilogue: scale to log2 domain, mask diagonal, per-tile max ----
    const bool isdiag = (br == bc);
    const int lr = lane >> 2;           // fragment row within 8
    const int lc = (lane & 3) * 2;      // fragment col pair base

    float m = -3.0e30f;
#pragma unroll
    for (int mi = 0; mi < 4; mi++)
#pragma unroll
        for (int ni = 0; ni < 4; ni++)
#pragma unroll
            for (int q = 0; q < 4; q++) {
                float x = acc[mi][ni][q] * SCALE2;
                if (isdiag) {
                    const int rloc = wm + mi * 16 + lr + ((q >> 1) << 3);
                    const int cloc = wn + ni * 8 + lc + (q & 1);
                    if (rloc == cloc) x = -3.0e30f;
                }
                acc[mi][ni][q] = x;
                m = fmaxf(m, x);
            }
#pragma unroll
    for (int off = 16; off >= 1; off >>= 1)
        m = fmaxf(m, __shfl_xor_sync(0xffffffffu, m, off));
    if (lane == 0) s_red[wid] = m;
    __syncthreads();
    float Mt = s_red[0];
#pragma unroll
    for (int w = 1; w < 8; w++) Mt = fmaxf(Mt, s_red[w]);

    // ---- exp + row/col partial sums from fragments ----
    float rs[4][2], cs[4][2];
#pragma unroll
    for (int i = 0; i < 4; i++) { rs[i][0] = rs[i][1] = 0.f; cs[i][0] = cs[i][1] = 0.f; }
#pragma unroll
    for (int mi = 0; mi < 4; mi++)
#pragma unroll
        for (int ni = 0; ni < 4; ni++) {
            float e0 = exp2_poly(acc[mi][ni][0] - Mt);
            float e1 = exp2_poly(acc[mi][ni][1] - Mt);
            float e2 = exp2_poly(acc[mi][ni][2] - Mt);
            float e3 = exp2_poly(acc[mi][ni][3] - Mt);
            rs[mi][0] += e0 + e1;  rs[mi][1] += e2 + e3;
            cs[ni][0] += e0 + e2;  cs[ni][1] += e1 + e3;
        }
    // row sums: reduce over the 4 lanes sharing a row (xor 1, 2)
#pragma unroll
    for (int off = 1; off <= 2; off <<= 1)
#pragma unroll
        for (int mi = 0; mi < 4; mi++)
#pragma unroll
            for (int h = 0; h < 2; h++)
                rs[mi][h] += __shfl_xor_sync(0xffffffffu, rs[mi][h], off);
    // col sums: reduce over the 8 lanes sharing a col pair (xor 4, 8, 16)
#pragma unroll
    for (int off = 4; off <= 16; off <<= 1)
#pragma unroll
        for (int ni = 0; ni < 4; ni++)
#pragma unroll
            for (int p = 0; p < 2; p++)
                cs[ni][p] += __shfl_xor_sync(0xffffffffu, cs[ni][p], off);

    if ((lane & 3) == 0) {
#pragma unroll
        for (int mi = 0; mi < 4; mi++)
#pragma unroll
            for (int h = 0; h < 2; h++)
                s_row[wm + mi * 16 + lr + 8 * h][wid & 3] = rs[mi][h];
    }
    if (lane < 4) {
#pragma unroll
        for (int ni = 0; ni < 4; ni++)
#pragma unroll
            for (int p = 0; p < 2; p++)
                s_col[wn + ni * 8 + 2 * lane + p][wid >> 2] = cs[ni][p];
    }
    __syncthreads();

    if (tid < BMN) {
        const float rsum = s_row[tid][0] + s_row[tid][1] + s_row[tid][2] + s_row[tid][3];
        const int gr = br * BMN + tid;
        g_pm[gr * NTILES + bc] = Mt;
        g_ps[gr * NTILES + bc] = rsum;
    } else if (!isdiag) {
        const int cc = tid - BMN;
        const float csum = s_col[cc][0] + s_col[cc][1];
        const int gc = bc * BMN + cc;
        g_pm[gc * NTILES + br] = Mt;
        g_ps[gc * NTILES + br] = csum;
    }
}

// One warp per row: merge 64 (m2, s) partials (base-2) -> lse; positive dot.
__global__ void finalize_kernel(const float* __restrict__ zi, const float* __restrict__ zj) {
    const int warp = (blockIdx.x * blockDim.x + threadIdx.x) >> 5;
    const int lane = threadIdx.x & 31;
    if (warp >= TWO_N) return;
    const int r = warp;

    const float m0 = g_pm[r * NTILES + lane];
    const float m1 = g_pm[r * NTILES + 32 + lane];
    const float s0 = g_ps[r * NTILES + lane];
    const float s1 = g_ps[r * NTILES + 32 + lane];
    float m = fmaxf(m0, m1);
#pragma unroll
    for (int off = 16; off >= 1; off >>= 1)
        m = fmaxf(m, __shfl_xor_sync(0xffffffffu, m, off));
    float S = s0 * exp2f(m0 - m) + s1 * exp2f(m1 - m);
#pragma unroll
    for (int off = 16; off >= 1; off >>= 1)
        S += __shfl_xor_sync(0xffffffffu, S, off);

    const int p = (r < NN) ? r + NN : r - NN;
    const float* a = zrow(zi, zj, r);
    const float* b = zrow(zi, zj, p);
    float dot = 0.f;
#pragma unroll
    for (int q = 0; q < 2; q++) {
        const int k = lane * 8 + q * 4;
        float4 x = *(const float4*)(a + k);
        float4 y = *(const float4*)(b + k);
        dot += x.x * y.x + x.y * y.y + x.z * y.z + x.w * y.w;
    }
#pragma unroll
    for (int off = 16; off >= 1; off >>= 1)
        dot += __shfl_xor_sync(0xffffffffu, dot, off);

    if (lane == 0)
        g_rowv[r] = (m + log2f(S)) * LN2F - dot * 2.0f;
}

__global__ void reduce_kernel(float* __restrict__ out) {
    __shared__ float sm[8];
    float s = 0.f;
    for (int i = threadIdx.x; i < TWO_N; i += 256) s += g_rowv[i];
#pragma unroll
    for (int off = 16; off >= 1; off >>= 1)
        s += __shfl_xor_sync(0xffffffffu, s, off);
    if ((threadIdx.x & 31) == 0) sm[threadIdx.x >> 5] = s;
    __syncthreads();
    if (threadIdx.x < 8) {
        s = sm[threadIdx.x];
#pragma unroll
        for (int off = 4; off >= 1; off >>= 1)
            s += __shfl_xor_sync(0x000000ffu, s, off);
        if (threadIdx.x == 0) out[0] = s / (float)TWO_N;
    }
}

extern "C" void kernel_launch(void* const* d_in, const int* in_sizes, int n_in,
                              void* d_out, int out_size) {
    const float* zi = (const float*)d_in[0];
    const float* zj = (const float*)d_in[1];
    float* out = (float*)d_out;

    // Opt into >48KB dynamic smem, only when not capturing (correctness run
    // precedes capture, so the attribute is set before the graph records).
    cudaStreamCaptureStatus st = cudaStreamCaptureStatusNone;
    cudaError_t qe = cudaStreamIsCapturing(0, &st);
    if (qe == cudaSuccess && st == cudaStreamCaptureStatusNone) {
        cudaFuncSetAttribute(tile_kernel,
                             cudaFuncAttributeMaxDynamicSharedMemorySize, DYN_BYTES);
    } else {
        cudaGetLastError();
    }

    dim3 grid1(NTILES, NTILES);
    tile_kernel<<<grid1, 256, DYN_BYTES>>>(zi, zj);
    finalize_kernel<<<(TWO_N * 32) / 256, 256>>>(zi, zj);
    reduce_kernel<<<1, 256>>>(out);
}

// round 7
// speedup vs baseline: 1.9442x; 1.3963x over previous
#include <cuda_runtime.h>
#include <cuda_bf16.h>
#include <cstdint>

#define NN      4096
#define DD      256
#define TWO_N   8192
#define NTILES  64
#define NBLK    2080        // NTILES*(NTILES+1)/2 upper-tri tiles
#define BMN     128
#define KC      64          // K-chunk (bf16 elems) -> 128B rows, SW128-style swizzle
#define NCHUNK  4           // DD / KC
#define SCALE2  2.8853900817779268f   // (1/T) * log2(e) = 2 * 1.44269504
#define LN2F    0.6931471805599453f

#define TILE_BYTES 16384                  // 128 rows x 64 bf16 x 2B
#define BUF_BYTES  (4 * TILE_BYTES)       // Ahi, Alo, Bhi, Blo
#define DYN_BYTES  (2 * BUF_BYTES + 1024) // double-buffered

// pre-split bf16 operands
__device__ __nv_bfloat16 g_zhi[TWO_N * DD];
__device__ __nv_bfloat16 g_zlo[TWO_N * DD];
// scratch partials (base-2 domain): (m2, sum 2^(x2-m2)) per (row, tile-slot)
__device__ float g_pm[TWO_N * NTILES];
__device__ float g_ps[TWO_N * NTILES];
__device__ float g_rowv[TWO_N];

// ---------------- helpers (portable PTX: ldmatrix + mma.sync + cp.async) ----
__device__ __forceinline__ uint32_t smem_u32(const void* p) {
    uint32_t a;
    asm("{ .reg .u64 t; cvta.to.shared.u64 t, %1; cvt.u32.u64 %0, t; }" : "=r"(a) : "l"(p));
    return a;
}
#define SWZ(o) ((o) ^ (((o) >> 3) & 0x70))
#define CPASYNC16(dst, src) \
    asm volatile("cp.async.cg.shared.global [%0], [%1], 16;" :: "r"(dst), "l"(src) : "memory")
#define CPASYNC_COMMIT() asm volatile("cp.async.commit_group;" ::: "memory")
#define CPASYNC_WAIT(n)  asm volatile("cp.async.wait_group %0;" :: "n"(n) : "memory")
#define LDM_X4(r, a) \
    asm volatile("ldmatrix.sync.aligned.m8n8.x4.shared.b16 {%0,%1,%2,%3}, [%4];" \
        : "=r"((r)[0]), "=r"((r)[1]), "=r"((r)[2]), "=r"((r)[3]) : "r"(a))
#define LDM_X2(r, a) \
    asm volatile("ldmatrix.sync.aligned.m8n8.x2.shared.b16 {%0,%1}, [%2];" \
        : "=r"((r)[0]), "=r"((r)[1]) : "r"(a))
#define MMA16816(c, a, b) \
    asm volatile("mma.sync.aligned.m16n8k16.row.col.f32.bf16.bf16.f32 " \
        "{%0,%1,%2,%3}, {%4,%5,%6,%7}, {%8,%9}, {%0,%1,%2,%3};" \
        : "+f"((c)[0]), "+f"((c)[1]), "+f"((c)[2]), "+f"((c)[3]) \
        : "r"((a)[0]), "r"((a)[1]), "r"((a)[2]), "r"((a)[3]), "r"((b)[0]), "r"((b)[1]))

__device__ __forceinline__ const float* zrow(const float* zi, const float* zj, int r) {
    return (r < NN) ? (zi + (long)r * DD) : (zj + (long)(r - NN) * DD);
}

// exp2 for u <= 0, FMA-pipe only (no MUFU). ~3e-5 rel err.
__device__ __forceinline__ float exp2_poly(float u) {
    u = fmaxf(u, -126.0f);
    float n = floorf(u);
    float f = u - n;
    float p = fmaf(f, 0.000154035304f, 0.00133335581f);
    p = fmaf(p, f, 0.00961812911f);
    p = fmaf(p, f, 0.0555041087f);
    p = fmaf(p, f, 0.240226507f);
    p = fmaf(p, f, 0.693147181f);
    p = fmaf(p, f, 1.0f);
    return __int_as_float(((int)n + 127) << 23) * p;
}

// ---- pre-pass: split fp32 z into (hi, lo) bf16 arrays; 8 elems/thread ----
__global__ void convert_kernel(const float* __restrict__ zi, const float* __restrict__ zj) {
    const long base = ((long)blockIdx.x * blockDim.x + threadIdx.x) * 8;
    if (base >= (long)TWO_N * DD) return;
    const float* src = (base < (long)NN * DD) ? (zi + base) : (zj + base - (long)NN * DD);
    float4 a = *(const float4*)(src);
    float4 b = *(const float4*)(src + 4);
    __nv_bfloat16 h[8];
    float v[8] = {a.x, a.y, a.z, a.w, b.x, b.y, b.z, b.w};
#pragma unroll
    for (int i = 0; i < 8; i++) h[i] = __float2bfloat16_rn(v[i]);
    __nv_bfloat162 hp[4], lp[4];
#pragma unroll
    for (int i = 0; i < 4; i++) {
        hp[i] = __halves2bfloat162(h[2 * i], h[2 * i + 1]);
        lp[i] = __floats2bfloat162_rn(v[2 * i]     - __bfloat162float(h[2 * i]),
                                      v[2 * i + 1] - __bfloat162float(h[2 * i + 1]));
    }
    *(uint4*)(g_zhi + base) = *(uint4*)hp;
    *(uint4*)(g_zlo + base) = *(uint4*)lp;
}

// stage one 64-K chunk (A hi/lo + B hi/lo) into one smem buffer via cp.async
__device__ __forceinline__ void stage_chunk(uint32_t buf,
                                            const __nv_bfloat16* Ahg, const __nv_bfloat16* Alg,
                                            const __nv_bfloat16* Bhg, const __nv_bfloat16* Blg,
                                            int tid, int c) {
    const int row  = tid >> 1;
    const int half = tid & 1;
    const long goff = (long)row * DD + (long)c * KC + half * 32;
    const uint32_t rowbase = (uint32_t)row * 128u + (uint32_t)half * 64u;
#pragma unroll
    for (int i = 0; i < 4; i++) {
        const uint32_t sw = SWZ(rowbase + (uint32_t)i * 16u);
        CPASYNC16(buf                  + sw, Ahg + goff + i * 8);
        CPASYNC16(buf +     TILE_BYTES + sw, Alg + goff + i * 8);
        CPASYNC16(buf + 2 * TILE_BYTES + sw, Bhg + goff + i * 8);
        CPASYNC16(buf + 3 * TILE_BYTES + sw, Blg + goff + i * 8);
    }
}

__global__ __launch_bounds__(256)
void tile_kernel() {
    // triangular decode: block t -> (br, bc), bc >= br
    const int t = blockIdx.x;
    const float fN = (float)NTILES + 0.5f;
    int br = (int)(fN - sqrtf(fmaxf(fN * fN - 2.0f * (float)t, 0.0f)));
    if (br > NTILES - 1) br = NTILES - 1;
    if (br < 0) br = 0;
    while ((br + 1) * NTILES - ((br + 1) * br) / 2 <= t) br++;
    while (br * NTILES - (br * (br - 1)) / 2 > t) br--;
    const int bc = br + (t - (br * NTILES - (br * (br - 1)) / 2));

    extern __shared__ char dynsmem[];
    __shared__ float s_row[BMN][4];   // row partial sums per warp_n
    __shared__ float s_col[BMN][2];   // col partial sums per warp_m
    __shared__ float s_red[8];

    const int tid  = threadIdx.x;
    const int wid  = tid >> 5;
    const int lane = tid & 31;
    const int wm   = (wid >> 2) * 64;   // warp row offset
    const int wn   = (wid & 3) * 32;    // warp col offset

    const uint32_t dynbase = (smem_u32(dynsmem) + 1023u) & ~1023u;

    const __nv_bfloat16* Ahg = g_zhi + (long)(br * BMN) * DD;
    const __nv_bfloat16* Alg = g_zlo + (long)(br * BMN) * DD;
    const __nv_bfloat16* Bhg = g_zhi + (long)(bc * BMN) * DD;
    const __nv_bfloat16* Blg = g_zlo + (long)(bc * BMN) * DD;

    // per-lane ldmatrix constants (SW128 xor mask constant per lane)
    const int rA  = lane & 15;
    const uint32_t kbA  = (uint32_t)((lane >> 4) * 16);
    const uint32_t xorA = (uint32_t)((rA & 7) << 4);
    const int rB  = lane & 7;
    const uint32_t kbB  = (uint32_t)(((lane >> 3) & 1) * 16);
    const uint32_t xorB = (uint32_t)(rB << 4);
    uint32_t ArowB[4], BrowB[4];
#pragma unroll
    for (int mi = 0; mi < 4; mi++) ArowB[mi] = (uint32_t)((wm + mi * 16 + rA) * 128);
#pragma unroll
    for (int ni = 0; ni < 4; ni++) BrowB[ni] = (uint32_t)((wn + ni * 8 + rB) * 128);

    float acc[4][4][4];
#pragma unroll
    for (int mi = 0; mi < 4; mi++)
#pragma unroll
        for (int ni = 0; ni < 4; ni++)
#pragma unroll
            for (int q = 0; q < 4; q++) acc[mi][ni][q] = 0.f;

    // ---- pipelined mainloop: cp.async double buffer ----
    stage_chunk(dynbase, Ahg, Alg, Bhg, Blg, tid, 0);
    CPASYNC_COMMIT();

#pragma unroll 1
    for (int c = 0; c < NCHUNK; c++) {
        const uint32_t buf = dynbase + (uint32_t)(c & 1) * BUF_BYTES;
        if (c < NCHUNK - 1) {
            stage_chunk(dynbase + (uint32_t)((c + 1) & 1) * BUF_BYTES,
                        Ahg, Alg, Bhg, Blg, tid, c + 1);
            CPASYNC_COMMIT();
            CPASYNC_WAIT(1);
        } else {
            CPASYNC_WAIT(0);
        }
        __syncthreads();

        const uint32_t Ahi = buf,                  Alo = buf + TILE_BYTES;
        const uint32_t Bhi = buf + 2 * TILE_BYTES, Blo = buf + 3 * TILE_BYTES;
#pragma unroll
        for (int ks = 0; ks < 4; ks++) {
            const uint32_t kA = ((uint32_t)(ks * 32) + kbA) ^ xorA;
            const uint32_t kB = ((uint32_t)(ks * 32) + kbB) ^ xorB;
            uint32_t ah[4][4], al[4][4], bh[4][2], bl[4][2];
#pragma unroll
            for (int mi = 0; mi < 4; mi++) {
                const uint32_t off = ArowB[mi] + kA;
                LDM_X4(ah[mi], Ahi + off);
                LDM_X4(al[mi], Alo + off);
            }
#pragma unroll
            for (int ni = 0; ni < 4; ni++) {
                const uint32_t off = BrowB[ni] + kB;
                LDM_X2(bh[ni], Bhi + off);
                LDM_X2(bl[ni], Blo + off);
            }
#pragma unroll
            for (int mi = 0; mi < 4; mi++)
#pragma unroll
                for (int ni = 0; ni < 4; ni++) {
                    MMA16816(acc[mi][ni], ah[mi], bh[ni]);
                    MMA16816(acc[mi][ni], ah[mi], bl[ni]);
                    MMA16816(acc[mi][ni], al[mi], bh[ni]);
                }
        }
        __syncthreads();
    }

    // ---- epilogue: scale to log2 domain, mask diagonal, per-tile max ----
    const bool isdiag = (br == bc);
    const int lr = lane >> 2;
    const int lc = (lane & 3) * 2;

    float m = -3.0e30f;
#pragma unroll
    for (int mi = 0; mi < 4; mi++)
#pragma unroll
        for (int ni = 0; ni < 4; ni++)
#pragma unroll
            for (int q = 0; q < 4; q++) {
                float x = acc[mi][ni][q] * SCALE2;
                if (isdiag) {
                    const int rloc = wm + mi * 16 + lr + ((q >> 1) << 3);
                    const int cloc = wn + ni * 8 + lc + (q & 1);
                    if (rloc == cloc) x = -3.0e30f;
                }
                acc[mi][ni][q] = x;
                m = fmaxf(m, x);
            }
#pragma unroll
    for (int off = 16; off >= 1; off >>= 1)
        m = fmaxf(m, __shfl_xor_sync(0xffffffffu, m, off));
    if (lane == 0) s_red[wid] = m;
    __syncthreads();
    float Mt = s_red[0];
#pragma unroll
    for (int w = 1; w < 8; w++) Mt = fmaxf(Mt, s_red[w]);

    // ---- exp + row/col partial sums from fragments ----
    float rs[4][2], cs[4][2];
#pragma unroll
    for (int i = 0; i < 4; i++) { rs[i][0] = rs[i][1] = 0.f; cs[i][0] = cs[i][1] = 0.f; }
#pragma unroll
    for (int mi = 0; mi < 4; mi++)
#pragma unroll
        for (int ni = 0; ni < 4; ni++) {
            float e0 = exp2_poly(acc[mi][ni][0] - Mt);
            float e1 = exp2_poly(acc[mi][ni][1] - Mt);
            float e2 = exp2_poly(acc[mi][ni][2] - Mt);
            float e3 = exp2_poly(acc[mi][ni][3] - Mt);
            rs[mi][0] += e0 + e1;  rs[mi][1] += e2 + e3;
            cs[ni][0] += e0 + e2;  cs[ni][1] += e1 + e3;
        }
#pragma unroll
    for (int off = 1; off <= 2; off <<= 1)
#pragma unroll
        for (int mi = 0; mi < 4; mi++)
#pragma unroll
            for (int h = 0; h < 2; h++)
                rs[mi][h] += __shfl_xor_sync(0xffffffffu, rs[mi][h], off);
#pragma unroll
    for (int off = 4; off <= 16; off <<= 1)
#pragma unroll
        for (int ni = 0; ni < 4; ni++)
#pragma unroll
            for (int p = 0; p < 2; p++)
                cs[ni][p] += __shfl_xor_sync(0xffffffffu, cs[ni][p], off);

    if ((lane & 3) == 0) {
#pragma unroll
        for (int mi = 0; mi < 4; mi++)
#pragma unroll
            for (int h = 0; h < 2; h++)
                s_row[wm + mi * 16 + lr + 8 * h][wid & 3] = rs[mi][h];
    }
    if (lane < 4) {
#pragma unroll
        for (int ni = 0; ni < 4; ni++)
#pragma unroll
            for (int p = 0; p < 2; p++)
                s_col[wn + ni * 8 + 2 * lane + p][wid >> 2] = cs[ni][p];
    }
    __syncthreads();

    if (tid < BMN) {
        const float rsum = s_row[tid][0] + s_row[tid][1] + s_row[tid][2] + s_row[tid][3];
        const int gr = br * BMN + tid;
        g_pm[gr * NTILES + bc] = Mt;
        g_ps[gr * NTILES + bc] = rsum;
    } else if (!isdiag) {
        const int cc = tid - BMN;
        const float csum = s_col[cc][0] + s_col[cc][1];
        const int gc = bc * BMN + cc;
        g_pm[gc * NTILES + br] = Mt;
        g_ps[gc * NTILES + br] = csum;
    }
}

// One warp per row: merge 64 (m2, s) partials (base-2) -> lse; positive dot.
__global__ void finalize_kernel(const float* __restrict__ zi, const float* __restrict__ zj) {
    const int warp = (blockIdx.x * blockDim.x + threadIdx.x) >> 5;
    const int lane = threadIdx.x & 31;
    if (warp >= TWO_N) return;
    const int r = warp;

    const float m0 = g_pm[r * NTILES + lane];
    const float m1 = g_pm[r * NTILES + 32 + lane];
    const float s0 = g_ps[r * NTILES + lane];
    const float s1 = g_ps[r * NTILES + 32 + lane];
    float m = fmaxf(m0, m1);
#pragma unroll
    for (int off = 16; off >= 1; off >>= 1)
        m = fmaxf(m, __shfl_xor_sync(0xffffffffu, m, off));
    float S = s0 * exp2f(m0 - m) + s1 * exp2f(m1 - m);
#pragma unroll
    for (int off = 16; off >= 1; off >>= 1)
        S += __shfl_xor_sync(0xffffffffu, S, off);

    const int p = (r < NN) ? r + NN : r - NN;
    const float* a = zrow(zi, zj, r);
    const float* b = zrow(zi, zj, p);
    float dot = 0.f;
#pragma unroll
    for (int q = 0; q < 2; q++) {
        const int k = lane * 8 + q * 4;
        float4 x = *(const float4*)(a + k);
        float4 y = *(const float4*)(b + k);
        dot += x.x * y.x + x.y * y.y + x.z * y.z + x.w * y.w;
    }
#pragma unroll
    for (int off = 16; off >= 1; off >>= 1)
        dot += __shfl_xor_sync(0xffffffffu, dot, off);

    if (lane == 0)
        g_rowv[r] = (m + log2f(S)) * LN2F - dot * 2.0f;
}

__global__ void reduce_kernel(float* __restrict__ out) {
    __shared__ float sm[8];
    float s = 0.f;
    for (int i = threadIdx.x; i < TWO_N; i += 256) s += g_rowv[i];
#pragma unroll
    for (int off = 16; off >= 1; off >>= 1)
        s += __shfl_xor_sync(0xffffffffu, s, off);
    if ((threadIdx.x & 31) == 0) sm[threadIdx.x >> 5] = s;
    __syncthreads();
    if (threadIdx.x < 8) {
        s = sm[threadIdx.x];
#pragma unroll
        for (int off = 4; off >= 1; off >>= 1)
            s += __shfl_xor_sync(0x000000ffu, s, off);
        if (threadIdx.x == 0) out[0] = s / (float)TWO_N;
    }
}

extern "C" void kernel_launch(void* const* d_in, const int* in_sizes, int n_in,
                              void* d_out, int out_size) {
    const float* zi = (const float*)d_in[0];
    const float* zj = (const float*)d_in[1];
    float* out = (float*)d_out;

    // Opt into >48KB dynamic smem, only when not capturing (correctness run
    // precedes capture, so the attribute is set before the graph records).
    cudaStreamCaptureStatus st = cudaStreamCaptureStatusNone;
    cudaError_t qe = cudaStreamIsCapturing(0, &st);
    if (qe == cudaSuccess && st == cudaStreamCaptureStatusNone) {
        cudaFuncSetAttribute(tile_kernel,
                             cudaFuncAttributeMaxDynamicSharedMemorySize, DYN_BYTES);
    } else {
        cudaGetLastError();
    }

    convert_kernel<<<(TWO_N * DD / 8 + 255) / 256, 256>>>(zi, zj);
    tile_kernel<<<NBLK, 256, DYN_BYTES>>>();
    finalize_kernel<<<(TWO_N * 32) / 256, 256>>>(zi, zj);
    reduce_kernel<<<1, 256>>>(out);
}

// round 8
// speedup vs baseline: 2.0353x; 1.0469x over previous
#include <cuda_runtime.h>
#include <cuda_bf16.h>
#include <cstdint>

#define NN      4096
#define DD      256
#define TWO_N   8192
#define NTILES  64
#define NBLK    2080        // NTILES*(NTILES+1)/2 upper-tri tiles
#define BMN     128
#define KC      32          // K-chunk (tf32 elems) -> 128B rows, 16B-atom swizzle
#define NCHUNK  8           // DD / KC
#define SCALE2  2.8853900817779268f   // (1/T) * log2(e) = 2 * 1.44269504
#define LN2F    0.6931471805599453f

#define TILE_BYTES 16384                  // 128 rows x 32 tf32 x 4B
#define BUF_BYTES  (2 * TILE_BYTES)       // A, B
#define DYN_BYTES  (2 * BUF_BYTES + 1024) // double-buffered

// z rounded to tf32 (rna), row-major [TWO_N][DD]
__device__ float g_zt[TWO_N * DD];
// scratch partials (base-2 domain): (m2, sum 2^(x2-m2)) per (row, tile-slot)
__device__ float g_pm[TWO_N * NTILES];
__device__ float g_ps[TWO_N * NTILES];
__device__ float g_rowv[TWO_N];

// ---------------- helpers (portable PTX: ldmatrix + mma.sync + cp.async) ----
__device__ __forceinline__ uint32_t smem_u32(const void* p) {
    uint32_t a;
    asm("{ .reg .u64 t; cvta.to.shared.u64 t, %1; cvt.u32.u64 %0, t; }" : "=r"(a) : "l"(p));
    return a;
}
#define SWZ(o) ((o) ^ (((o) >> 3) & 0x70))
#define CPASYNC16(dst, src) \
    asm volatile("cp.async.cg.shared.global [%0], [%1], 16;" :: "r"(dst), "l"(src) : "memory")
#define CPASYNC_COMMIT() asm volatile("cp.async.commit_group;" ::: "memory")
#define CPASYNC_WAIT(n)  asm volatile("cp.async.wait_group %0;" :: "n"(n) : "memory")
#define LDM_X4(r, a) \
    asm volatile("ldmatrix.sync.aligned.m8n8.x4.shared.b16 {%0,%1,%2,%3}, [%4];" \
        : "=r"((r)[0]), "=r"((r)[1]), "=r"((r)[2]), "=r"((r)[3]) : "r"(a))
#define LDM_X2(r, a) \
    asm volatile("ldmatrix.sync.aligned.m8n8.x2.shared.b16 {%0,%1}, [%2];" \
        : "=r"((r)[0]), "=r"((r)[1]) : "r"(a))
#define MMA1688TF32(c, a, b) \
    asm volatile("mma.sync.aligned.m16n8k8.row.col.f32.tf32.tf32.f32 " \
        "{%0,%1,%2,%3}, {%4,%5,%6,%7}, {%8,%9}, {%0,%1,%2,%3};" \
        : "+f"((c)[0]), "+f"((c)[1]), "+f"((c)[2]), "+f"((c)[3]) \
        : "r"((a)[0]), "r"((a)[1]), "r"((a)[2]), "r"((a)[3]), "r"((b)[0]), "r"((b)[1]))

__device__ __forceinline__ const float* zrow(const float* zi, const float* zj, int r) {
    return (r < NN) ? (zi + (long)r * DD) : (zj + (long)(r - NN) * DD);
}

// exp2 for u <= 0, FMA-pipe only (no MUFU). ~3e-5 rel err.
__device__ __forceinline__ float exp2_poly(float u) {
    u = fmaxf(u, -126.0f);
    float n = floorf(u);
    float f = u - n;
    float p = fmaf(f, 0.000154035304f, 0.00133335581f);
    p = fmaf(p, f, 0.00961812911f);
    p = fmaf(p, f, 0.0555041087f);
    p = fmaf(p, f, 0.240226507f);
    p = fmaf(p, f, 0.693147181f);
    p = fmaf(p, f, 1.0f);
    return __int_as_float(((int)n + 127) << 23) * p;
}

// ---- pre-pass: round z to tf32 (rna), 8 elems/thread ----
__global__ void convert_kernel(const float* __restrict__ zi, const float* __restrict__ zj) {
    const long base = ((long)blockIdx.x * blockDim.x + threadIdx.x) * 8;
    if (base >= (long)TWO_N * DD) return;
    const float* src = (base < (long)NN * DD) ? (zi + base) : (zj + base - (long)NN * DD);
    float4 a = *(const float4*)(src);
    float4 b = *(const float4*)(src + 4);
    uint32_t t[8];
    float v[8] = {a.x, a.y, a.z, a.w, b.x, b.y, b.z, b.w};
#pragma unroll
    for (int i = 0; i < 8; i++)
        asm("cvt.rna.tf32.f32 %0, %1;" : "=r"(t[i]) : "f"(v[i]));
    *(uint4*)(g_zt + base)     = *(uint4*)&t[0];
    *(uint4*)(g_zt + base + 4) = *(uint4*)&t[4];
}

// stage one 32-K chunk (A + B tiles) into one smem buffer via cp.async
__device__ __forceinline__ void stage_chunk(uint32_t buf,
                                            const float* Ag, const float* Bg,
                                            int tid, int c) {
    const int half = tid >> 7;          // 0 = A tile, 1 = B tile
    const int row  = tid & 127;
    const float* g = (half ? Bg : Ag) + (long)row * DD + (long)c * KC;
    const uint32_t base = buf + (uint32_t)half * TILE_BYTES + 0u;
    const uint32_t rowbase = (uint32_t)row * 128u;
#pragma unroll
    for (int i = 0; i < 8; i++) {
        const uint32_t sw = SWZ(rowbase + (uint32_t)i * 16u);
        CPASYNC16(base + sw, g + i * 4);
    }
}

__global__ __launch_bounds__(256, 2)
void tile_kernel() {
    // triangular decode: block t -> (br, bc), bc >= br
    const int t = blockIdx.x;
    const float fN = (float)NTILES + 0.5f;
    int br = (int)(fN - sqrtf(fmaxf(fN * fN - 2.0f * (float)t, 0.0f)));
    if (br > NTILES - 1) br = NTILES - 1;
    if (br < 0) br = 0;
    while ((br + 1) * NTILES - ((br + 1) * br) / 2 <= t) br++;
    while (br * NTILES - (br * (br - 1)) / 2 > t) br--;
    const int bc = br + (t - (br * NTILES - (br * (br - 1)) / 2));

    extern __shared__ char dynsmem[];
    __shared__ float s_row[BMN][4];   // row partial sums per warp_n
    __shared__ float s_col[BMN][2];   // col partial sums per warp_m
    __shared__ float s_red[8];

    const int tid  = threadIdx.x;
    const int wid  = tid >> 5;
    const int lane = tid & 31;
    const int wm   = (wid >> 2) * 64;   // warp row offset
    const int wn   = (wid & 3) * 32;    // warp col offset

    const uint32_t dynbase = (smem_u32(dynsmem) + 1023u) & ~1023u;

    const float* Ag = g_zt + (long)(br * BMN) * DD;
    const float* Bg = g_zt + (long)(bc * BMN) * DD;

    // per-lane ldmatrix constants (16B-atom swizzle xor mask constant per lane)
    const int rA  = lane & 15;
    const uint32_t kbA  = (uint32_t)((lane >> 4) * 16);
    const uint32_t xorA = (uint32_t)((rA & 7) << 4);
    const int rB  = lane & 7;
    const uint32_t kbB  = (uint32_t)(((lane >> 3) & 1) * 16);
    const uint32_t xorB = (uint32_t)(rB << 4);
    uint32_t ArowB[4], BrowB[4];
#pragma unroll
    for (int mi = 0; mi < 4; mi++) ArowB[mi] = (uint32_t)((wm + mi * 16 + rA) * 128);
#pragma unroll
    for (int ni = 0; ni < 4; ni++) BrowB[ni] = (uint32_t)((wn + ni * 8 + rB) * 128);

    float acc[4][4][4];
#pragma unroll
    for (int mi = 0; mi < 4; mi++)
#pragma unroll
        for (int ni = 0; ni < 4; ni++)
#pragma unroll
            for (int q = 0; q < 4; q++) acc[mi][ni][q] = 0.f;

    // ---- pipelined mainloop: cp.async double buffer ----
    stage_chunk(dynbase, Ag, Bg, tid, 0);
    CPASYNC_COMMIT();

#pragma unroll 1
    for (int c = 0; c < NCHUNK; c++) {
        const uint32_t buf = dynbase + (uint32_t)(c & 1) * BUF_BYTES;
        if (c < NCHUNK - 1) {
            stage_chunk(dynbase + (uint32_t)((c + 1) & 1) * BUF_BYTES, Ag, Bg, tid, c + 1);
            CPASYNC_COMMIT();
            CPASYNC_WAIT(1);
        } else {
            CPASYNC_WAIT(0);
        }
        __syncthreads();

        const uint32_t At = buf;
        const uint32_t Bt = buf + TILE_BYTES;
#pragma unroll
        for (int ks = 0; ks < 4; ks++) {   // k = 8 tf32 per step = 32B
            const uint32_t kA = ((uint32_t)(ks * 32) + kbA) ^ xorA;
            const uint32_t kB = ((uint32_t)(ks * 32) + kbB) ^ xorB;
            uint32_t af[4][4], bf[4][2];
#pragma unroll
            for (int mi = 0; mi < 4; mi++) LDM_X4(af[mi], At + ArowB[mi] + kA);
#pragma unroll
            for (int ni = 0; ni < 4; ni++) LDM_X2(bf[ni], Bt + BrowB[ni] + kB);
#pragma unroll
            for (int mi = 0; mi < 4; mi++)
#pragma unroll
                for (int ni = 0; ni < 4; ni++)
                    MMA1688TF32(acc[mi][ni], af[mi], bf[ni]);
        }
        __syncthreads();
    }

    // ---- epilogue: scale to log2 domain, mask diagonal, per-tile max ----
    const bool isdiag = (br == bc);
    const int lr = lane >> 2;
    const int lc = (lane & 3) * 2;

    float m = -3.0e30f;
#pragma unroll
    for (int mi = 0; mi < 4; mi++)
#pragma unroll
        for (int ni = 0; ni < 4; ni++)
#pragma unroll
            for (int q = 0; q < 4; q++) {
                float x = acc[mi][ni][q] * SCALE2;
                if (isdiag) {
                    const int rloc = wm + mi * 16 + lr + ((q >> 1) << 3);
                    const int cloc = wn + ni * 8 + lc + (q & 1);
                    if (rloc == cloc) x = -3.0e30f;
                }
                acc[mi][ni][q] = x;
                m = fmaxf(m, x);
            }
#pragma unroll
    for (int off = 16; off >= 1; off >>= 1)
        m = fmaxf(m, __shfl_xor_sync(0xffffffffu, m, off));
    if (lane == 0) s_red[wid] = m;
    __syncthreads();
    float Mt = s_red[0];
#pragma unroll
    for (int w = 1; w < 8; w++) Mt = fmaxf(Mt, s_red[w]);

    // ---- exp + row/col partial sums from fragments ----
    float rs[4][2], cs[4][2];
#pragma unroll
    for (int i = 0; i < 4; i++) { rs[i][0] = rs[i][1] = 0.f; cs[i][0] = cs[i][1] = 0.f; }
#pragma unroll
    for (int mi = 0; mi < 4; mi++)
#pragma unroll
        for (int ni = 0; ni < 4; ni++) {
            float e0 = exp2_poly(acc[mi][ni][0] - Mt);
            float e1 = exp2_poly(acc[mi][ni][1] - Mt);
            float e2 = exp2_poly(acc[mi][ni][2] - Mt);
            float e3 = exp2_poly(acc[mi][ni][3] - Mt);
            rs[mi][0] += e0 + e1;  rs[mi][1] += e2 + e3;
            cs[ni][0] += e0 + e2;  cs[ni][1] += e1 + e3;
        }
#pragma unroll
    for (int off = 1; off <= 2; off <<= 1)
#pragma unroll
        for (int mi = 0; mi < 4; mi++)
#pragma unroll
            for (int h = 0; h < 2; h++)
                rs[mi][h] += __shfl_xor_sync(0xffffffffu, rs[mi][h], off);
#pragma unroll
    for (int off = 4; off <= 16; off <<= 1)
#pragma unroll
        for (int ni = 0; ni < 4; ni++)
#pragma unroll
            for (int p = 0; p < 2; p++)
                cs[ni][p] += __shfl_xor_sync(0xffffffffu, cs[ni][p], off);

    if ((lane & 3) == 0) {
#pragma unroll
        for (int mi = 0; mi < 4; mi++)
#pragma unroll
            for (int h = 0; h < 2; h++)
                s_row[wm + mi * 16 + lr + 8 * h][wid & 3] = rs[mi][h];
    }
    if (lane < 4) {
#pragma unroll
        for (int ni = 0; ni < 4; ni++)
#pragma unroll
            for (int p = 0; p < 2; p++)
                s_col[wn + ni * 8 + 2 * lane + p][wid >> 2] = cs[ni][p];
    }
    __syncthreads();

    if (tid < BMN) {
        const float rsum = s_row[tid][0] + s_row[tid][1] + s_row[tid][2] + s_row[tid][3];
        const int gr = br * BMN + tid;
        g_pm[gr * NTILES + bc] = Mt;
        g_ps[gr * NTILES + bc] = rsum;
    } else if (!isdiag) {
        const int cc = tid - BMN;
        const float csum = s_col[cc][0] + s_col[cc][1];
        const int gc = bc * BMN + cc;
        g_pm[gc * NTILES + br] = Mt;
        g_ps[gc * NTILES + br] = csum;
    }
}

// One warp per row: merge 64 (m2, s) partials (base-2) -> lse; positive dot.
__global__ void finalize_kernel(const float* __restrict__ zi, const float* __restrict__ zj) {
    const int warp = (blockIdx.x * blockDim.x + threadIdx.x) >> 5;
    const int lane = threadIdx.x & 31;
    if (warp >= TWO_N) return;
    const int r = warp;

    const float m0 = g_pm[r * NTILES + lane];
    const float m1 = g_pm[r * NTILES + 32 + lane];
    const float s0 = g_ps[r * NTILES + lane];
    const float s1 = g_ps[r * NTILES + 32 + lane];
    float m = fmaxf(m0, m1);
#pragma unroll
    for (int off = 16; off >= 1; off >>= 1)
        m = fmaxf(m, __shfl_xor_sync(0xffffffffu, m, off));
    float S = s0 * exp2f(m0 - m) + s1 * exp2f(m1 - m);
#pragma unroll
    for (int off = 16; off >= 1; off >>= 1)
        S += __shfl_xor_sync(0xffffffffu, S, off);

    const int p = (r < NN) ? r + NN : r - NN;
    const float* a = zrow(zi, zj, r);
    const float* b = zrow(zi, zj, p);
    float dot = 0.f;
#pragma unroll
    for (int q = 0; q < 2; q++) {
        const int k = lane * 8 + q * 4;
        float4 x = *(const float4*)(a + k);
        float4 y = *(const float4*)(b + k);
        dot += x.x * y.x + x.y * y.y + x.z * y.z + x.w * y.w;
    }
#pragma unroll
    for (int off = 16; off >= 1; off >>= 1)
        dot += __shfl_xor_sync(0xffffffffu, dot, off);

    if (lane == 0)
        g_rowv[r] = (m + log2f(S)) * LN2F - dot * 2.0f;
}

__global__ void reduce_kernel(float* __restrict__ out) {
    __shared__ float sm[8];
    float s = 0.f;
    for (int i = threadIdx.x; i < TWO_N; i += 256) s += g_rowv[i];
#pragma unroll
    for (int off = 16; off >= 1; off >>= 1)
        s += __shfl_xor_sync(0xffffffffu, s, off);
    if ((threadIdx.x & 31) == 0) sm[threadIdx.x >> 5] = s;
    __syncthreads();
    if (threadIdx.x < 8) {
        s = sm[threadIdx.x];
#pragma unroll
        for (int off = 4; off >= 1; off >>= 1)
            s += __shfl_xor_sync(0x000000ffu, s, off);
        if (threadIdx.x == 0) out[0] = s / (float)TWO_N;
    }
}

extern "C" void kernel_launch(void* const* d_in, const int* in_sizes, int n_in,
                              void* d_out, int out_size) {
    const float* zi = (const float*)d_in[0];
    const float* zj = (const float*)d_in[1];
    float* out = (float*)d_out;

    // Opt into >48KB dynamic smem, only when not capturing (correctness run
    // precedes capture, so the attribute is set before the graph records).
    cudaStreamCaptureStatus st = cudaStreamCaptureStatusNone;
    cudaError_t qe = cudaStreamIsCapturing(0, &st);
    if (qe == cudaSuccess && st == cudaStreamCaptureStatusNone) {
        cudaFuncSetAttribute(tile_kernel,
                             cudaFuncAttributeMaxDynamicSharedMemorySize, DYN_BYTES);
    } else {
        cudaGetLastError();
    }

    convert_kernel<<<(TWO_N * DD / 8 + 255) / 256, 256>>>(zi, zj);
    tile_kernel<<<NBLK, 256, DYN_BYTES>>>();
    finalize_kernel<<<(TWO_N * 32) / 256, 256>>>(zi, zj);
    reduce_kernel<<<1, 256>>>(out);
}

// round 9
// speedup vs baseline: 3.6039x; 1.7707x over previous
#include <cuda_runtime.h>
#include <cuda_bf16.h>
#include <cstdint>

#define NN      4096
#define DD      256
#define TWO_N   8192
#define NTILES  64
#define NBLK    2080        // NTILES*(NTILES+1)/2 upper-tri tiles
#define BMN     128
#define KC      32          // K-chunk (tf32) -> 128B rows, 16B-atom swizzle
#define NCHUNK  8           // DD / KC
#define NSTAGE  3
#define SCALE2  2.8853900817779268f   // (1/T) * log2(e)
#define LN2F    0.6931471805599453f

#define TILE_BYTES 16384                    // 128 rows x 32 tf32 x 4B
#define BUF_BYTES  (2 * TILE_BYTES)         // A, B per stage
#define DYN_BYTES  (NSTAGE * BUF_BYTES + 1024)

// z in tf32, PRE-SWIZZLED tile layout: [64 row-blocks][8 chunks][16KB tile]
// tile byte (row,col): SWZ(row*128 + col*4)
__device__ float g_zt[TWO_N * DD];
// scratch partials (base-2 domain)
__device__ float g_pm[TWO_N * NTILES];
__device__ float g_ps[TWO_N * NTILES];
__device__ float g_rowv[TWO_N];

// ---------------- helpers ----------------
__device__ __forceinline__ uint32_t smem_u32(const void* p) {
    uint32_t a;
    asm("{ .reg .u64 t; cvta.to.shared.u64 t, %1; cvt.u32.u64 %0, t; }" : "=r"(a) : "l"(p));
    return a;
}
#define SWZ(o) ((o) ^ (((o) >> 3) & 0x70))
#define MBAR_INIT(mb, c) asm volatile("mbarrier.init.shared.b64 [%0], %1;" :: "r"((uint32_t)(mb)), "r"((uint32_t)(c)) : "memory")
#define MBAR_EXPECT(mb, n) asm volatile("mbarrier.arrive.expect_tx.shared.b64 _, [%0], %1;" :: "r"((uint32_t)(mb)), "r"((uint32_t)(n)) : "memory")
#define BULK_G2S(dst, src, n, mb) \
    asm volatile("cp.async.bulk.shared::cluster.global.mbarrier::complete_tx::bytes [%0], [%1], %2, [%3];" \
        :: "r"((uint32_t)(dst)), "l"(src), "r"((uint32_t)(n)), "r"((uint32_t)(mb)) : "memory")
#define MBAR_WAIT(mb, ph) do {                                                   \
    uint32_t _m = (uint32_t)(mb), _p = (uint32_t)(ph), _d;                       \
    asm volatile("{\n\t.reg .pred p;\n\t"                                        \
        "mbarrier.try_wait.parity.acquire.cta.shared::cta.b64 p, [%1], %2;\n\t"  \
        "selp.b32 %0, 1, 0, p;\n\t}" : "=r"(_d) : "r"(_m), "r"(_p) : "memory");  \
    if (!_d) {                                                                   \
        asm volatile("{\n\t.reg .pred P1;\n\tWL_%=:\n\t"                         \
            "mbarrier.try_wait.parity.acquire.cta.shared::cta.b64 P1, [%0], %1, 0x989680;\n\t" \
            "@P1 bra.uni WD_%=;\n\tbra.uni WL_%=;\n\tWD_%=:\n\t}"                \
            :: "r"(_m), "r"(_p) : "memory");                                     \
    } } while (0)
#define LDM_X4(r, a) \
    asm volatile("ldmatrix.sync.aligned.m8n8.x4.shared.b16 {%0,%1,%2,%3}, [%4];" \
        : "=r"((r)[0]), "=r"((r)[1]), "=r"((r)[2]), "=r"((r)[3]) : "r"(a))
#define LDM_X2(r, a) \
    asm volatile("ldmatrix.sync.aligned.m8n8.x2.shared.b16 {%0,%1}, [%2];" \
        : "=r"((r)[0]), "=r"((r)[1]) : "r"(a))
#define MMA1688TF32(c, a, b) \
    asm volatile("mma.sync.aligned.m16n8k8.row.col.f32.tf32.tf32.f32 " \
        "{%0,%1,%2,%3}, {%4,%5,%6,%7}, {%8,%9}, {%0,%1,%2,%3};" \
        : "+f"((c)[0]), "+f"((c)[1]), "+f"((c)[2]), "+f"((c)[3]) \
        : "r"((a)[0]), "r"((a)[1]), "r"((a)[2]), "r"((a)[3]), "r"((b)[0]), "r"((b)[1]))

__device__ __forceinline__ const float* zrow(const float* zi, const float* zj, int r) {
    return (r < NN) ? (zi + (long)r * DD) : (zj + (long)(r - NN) * DD);
}

// exp2 for u <= 0, FMA-pipe only. ~3e-5 rel err.
__device__ __forceinline__ float exp2_poly(float u) {
    u = fmaxf(u, -126.0f);
    float n = floorf(u);
    float f = u - n;
    float p = fmaf(f, 0.000154035304f, 0.00133335581f);
    p = fmaf(p, f, 0.00961812911f);
    p = fmaf(p, f, 0.0555041087f);
    p = fmaf(p, f, 0.240226507f);
    p = fmaf(p, f, 0.693147181f);
    p = fmaf(p, f, 1.0f);
    return __int_as_float(((int)n + 127) << 23) * p;
}

// ---- pre-pass: tf32-round z and write PRE-SWIZZLED tile layout ----
__global__ void convert_kernel(const float* __restrict__ zi, const float* __restrict__ zj) {
    const long idx8 = ((long)blockIdx.x * blockDim.x + threadIdx.x) * 8;
    if (idx8 >= (long)TWO_N * DD) return;
    const int r   = (int)(idx8 >> 8);      // DD = 256
    const int d0  = (int)(idx8 & 255);
    const float* src = zrow(zi, zj, r) + d0;
    float4 a = *(const float4*)(src);
    float4 b = *(const float4*)(src + 4);
    uint32_t t[8];
    float v[8] = {a.x, a.y, a.z, a.w, b.x, b.y, b.z, b.w};
#pragma unroll
    for (int i = 0; i < 8; i++)
        asm("cvt.rna.tf32.f32 %0, %1;" : "=r"(t[i]) : "f"(v[i]));

    const int rb   = r >> 7;
    const int row  = r & 127;
    const int ch   = d0 >> 5;
    const int col0 = d0 & 31;
    char* tile = (char*)g_zt + ((long)(rb * NCHUNK + ch) << 14);
    const uint32_t o = (uint32_t)(row * 128 + col0 * 4);
    *(uint4*)(tile + SWZ(o))      = *(uint4*)&t[0];
    *(uint4*)(tile + SWZ(o + 16)) = *(uint4*)&t[4];
}

__global__ __launch_bounds__(256, 2)
void tile_kernel() {
    // triangular decode: block t -> (br, bc), bc >= br
    const int t = blockIdx.x;
    const float fN = (float)NTILES + 0.5f;
    int br = (int)(fN - sqrtf(fmaxf(fN * fN - 2.0f * (float)t, 0.0f)));
    if (br > NTILES - 1) br = NTILES - 1;
    if (br < 0) br = 0;
    while ((br + 1) * NTILES - ((br + 1) * br) / 2 <= t) br++;
    while (br * NTILES - (br * (br - 1)) / 2 > t) br--;
    const int bc = br + (t - (br * NTILES - (br * (br - 1)) / 2));

    extern __shared__ char dynsmem[];
    __shared__ float s_row[BMN][4];
    __shared__ float s_col[BMN][2];
    __shared__ float s_red[8];
    __shared__ __align__(8) unsigned long long s_mbar[NSTAGE];

    const int tid  = threadIdx.x;
    const int wid  = tid >> 5;
    const int lane = tid & 31;
    const int wm   = (wid >> 2) * 64;
    const int wn   = (wid & 3) * 32;

    const uint32_t dynbase = (smem_u32(dynsmem) + 1023u) & ~1023u;
    uint32_t mbar[NSTAGE];
#pragma unroll
    for (int s = 0; s < NSTAGE; s++) mbar[s] = smem_u32(&s_mbar[s]);

    // swizzled-tile gmem bases for this block-row / block-col
    const char* Ag = (const char*)g_zt + ((long)(br * NCHUNK) << 14);
    const char* Bg = (const char*)g_zt + ((long)(bc * NCHUNK) << 14);

    if (tid == 0) {
#pragma unroll
        for (int s = 0; s < NSTAGE; s++) MBAR_INIT(mbar[s], 1);
    }
    __syncthreads();

    // prologue: stage chunks 0..2
    if (tid == 0) {
#pragma unroll
        for (int p = 0; p < NSTAGE; p++) {
            const uint32_t buf = dynbase + (uint32_t)p * BUF_BYTES;
            MBAR_EXPECT(mbar[p], BUF_BYTES);
            BULK_G2S(buf,              Ag + ((long)p << 14), TILE_BYTES, mbar[p]);
            BULK_G2S(buf + TILE_BYTES, Bg + ((long)p << 14), TILE_BYTES, mbar[p]);
        }
    }

    // per-lane ldmatrix constants
    const int rA  = lane & 15;
    const uint32_t kbA  = (uint32_t)((lane >> 4) * 16);
    const uint32_t xorA = (uint32_t)((rA & 7) << 4);
    const int rB  = lane & 7;
    const uint32_t kbB  = (uint32_t)(((lane >> 3) & 1) * 16);
    const uint32_t xorB = (uint32_t)(rB << 4);
    uint32_t ArowB[4], BrowB[4];
#pragma unroll
    for (int mi = 0; mi < 4; mi++) ArowB[mi] = (uint32_t)((wm + mi * 16 + rA) * 128);
#pragma unroll
    for (int ni = 0; ni < 4; ni++) BrowB[ni] = (uint32_t)((wn + ni * 8 + rB) * 128);

    float acc[4][4][4];
#pragma unroll
    for (int mi = 0; mi < 4; mi++)
#pragma unroll
        for (int ni = 0; ni < 4; ni++)
#pragma unroll
            for (int q = 0; q < 4; q++) acc[mi][ni][q] = 0.f;

    // ---- mainloop: 3-stage bulk-copy pipeline ----
#pragma unroll 1
    for (int c = 0; c < NCHUNK; c++) {
        const int s = c % NSTAGE;
        const uint32_t buf = dynbase + (uint32_t)s * BUF_BYTES;
        MBAR_WAIT(mbar[s], (c / NSTAGE) & 1);

        const uint32_t At = buf;
        const uint32_t Bt = buf + TILE_BYTES;
#pragma unroll
        for (int ks = 0; ks < 4; ks++) {
            const uint32_t kA = ((uint32_t)(ks * 32) + kbA) ^ xorA;
            const uint32_t kB = ((uint32_t)(ks * 32) + kbB) ^ xorB;
            uint32_t af[4][4], bf[4][2];
#pragma unroll
            for (int mi = 0; mi < 4; mi++) LDM_X4(af[mi], At + ArowB[mi] + kA);
#pragma unroll
            for (int ni = 0; ni < 4; ni++) LDM_X2(bf[ni], Bt + BrowB[ni] + kB);
#pragma unroll
            for (int mi = 0; mi < 4; mi++)
#pragma unroll
                for (int ni = 0; ni < 4; ni++)
                    MMA1688TF32(acc[mi][ni], af[mi], bf[ni]);
        }
        __syncthreads();   // all warps done reading stage s
        if (c + NSTAGE < NCHUNK && tid == 0) {
            MBAR_EXPECT(mbar[s], BUF_BYTES);
            BULK_G2S(buf,              Ag + ((long)(c + NSTAGE) << 14), TILE_BYTES, mbar[s]);
            BULK_G2S(buf + TILE_BYTES, Bg + ((long)(c + NSTAGE) << 14), TILE_BYTES, mbar[s]);
        }
    }

    // ---- epilogue ----
    const bool isdiag = (br == bc);
    const int lr = lane >> 2;
    const int lc = (lane & 3) * 2;

    float m = -3.0e30f;
#pragma unroll
    for (int mi = 0; mi < 4; mi++)
#pragma unroll
        for (int ni = 0; ni < 4; ni++)
#pragma unroll
            for (int q = 0; q < 4; q++) {
                float x = acc[mi][ni][q] * SCALE2;
                if (isdiag) {
                    const int rloc = wm + mi * 16 + lr + ((q >> 1) << 3);
                    const int cloc = wn + ni * 8 + lc + (q & 1);
                    if (rloc == cloc) x = -3.0e30f;
                }
                acc[mi][ni][q] = x;
                m = fmaxf(m, x);
            }
#pragma unroll
    for (int off = 16; off >= 1; off >>= 1)
        m = fmaxf(m, __shfl_xor_sync(0xffffffffu, m, off));
    if (lane == 0) s_red[wid] = m;
    __syncthreads();
    float Mt = s_red[0];
#pragma unroll
    for (int w = 1; w < 8; w++) Mt = fmaxf(Mt, s_red[w]);

    float rs[4][2], cs[4][2];
#pragma unroll
    for (int i = 0; i < 4; i++) { rs[i][0] = rs[i][1] = 0.f; cs[i][0] = cs[i][1] = 0.f; }
#pragma unroll
    for (int mi = 0; mi < 4; mi++)
#pragma unroll
        for (int ni = 0; ni < 4; ni++) {
            float e0 = exp2_poly(acc[mi][ni][0] - Mt);
            float e1 = exp2_poly(acc[mi][ni][1] - Mt);
            float e2 = exp2_poly(acc[mi][ni][2] - Mt);
            float e3 = exp2_poly(acc[mi][ni][3] - Mt);
            rs[mi][0] += e0 + e1;  rs[mi][1] += e2 + e3;
            cs[ni][0] += e0 + e2;  cs[ni][1] += e1 + e3;
        }
#pragma unroll
    for (int off = 1; off <= 2; off <<= 1)
#pragma unroll
        for (int mi = 0; mi < 4; mi++)
#pragma unroll
            for (int h = 0; h < 2; h++)
                rs[mi][h] += __shfl_xor_sync(0xffffffffu, rs[mi][h], off);
#pragma unroll
    for (int off = 4; off <= 16; off <<= 1)
#pragma unroll
        for (int ni = 0; ni < 4; ni++)
#pragma unroll
            for (int p = 0; p < 2; p++)
                cs[ni][p] += __shfl_xor_sync(0xffffffffu, cs[ni][p], off);

    if ((lane & 3) == 0) {
#pragma unroll
        for (int mi = 0; mi < 4; mi++)
#pragma unroll
            for (int h = 0; h < 2; h++)
                s_row[wm + mi * 16 + lr + 8 * h][wid & 3] = rs[mi][h];
    }
    if (lane < 4) {
#pragma unroll
        for (int ni = 0; ni < 4; ni++)
#pragma unroll
            for (int p = 0; p < 2; p++)
                s_col[wn + ni * 8 + 2 * lane + p][wid >> 2] = cs[ni][p];
    }
    __syncthreads();

    if (tid < BMN) {
        const float rsum = s_row[tid][0] + s_row[tid][1] + s_row[tid][2] + s_row[tid][3];
        const int gr = br * BMN + tid;
        g_pm[gr * NTILES + bc] = Mt;
        g_ps[gr * NTILES + bc] = rsum;
    } else if (!isdiag) {
        const int cc = tid - BMN;
        const float csum = s_col[cc][0] + s_col[cc][1];
        const int gc = bc * BMN + cc;
        g_pm[gc * NTILES + br] = Mt;
        g_ps[gc * NTILES + br] = csum;
    }
}

// One warp per row: merge 64 (m2, s) partials -> lse; positive dot.
__global__ void finalize_kernel(const float* __restrict__ zi, const float* __restrict__ zj) {
    const int warp = (blockIdx.x * blockDim.x + threadIdx.x) >> 5;
    const int lane = threadIdx.x & 31;
    if (warp >= TWO_N) return;
    const int r = warp;

    const float m0 = g_pm[r * NTILES + lane];
    const float m1 = g_pm[r * NTILES + 32 + lane];
    const float s0 = g_ps[r * NTILES + lane];
    const float s1 = g_ps[r * NTILES + 32 + lane];
    float m = fmaxf(m0, m1);
#pragma unroll
    for (int off = 16; off >= 1; off >>= 1)
        m = fmaxf(m, __shfl_xor_sync(0xffffffffu, m, off));
    float S = s0 * exp2f(m0 - m) + s1 * exp2f(m1 - m);
#pragma unroll
    for (int off = 16; off >= 1; off >>= 1)
        S += __shfl_xor_sync(0xffffffffu, S, off);

    const int p = (r < NN) ? r + NN : r - NN;
    const float* a = zrow(zi, zj, r);
    const float* b = zrow(zi, zj, p);
    float dot = 0.f;
#pragma unroll
    for (int q = 0; q < 2; q++) {
        const int k = lane * 8 + q * 4;
        float4 x = *(const float4*)(a + k);
        float4 y = *(const float4*)(b + k);
        dot += x.x * y.x + x.y * y.y + x.z * y.z + x.w * y.w;
    }
#pragma unroll
    for (int off = 16; off >= 1; off >>= 1)
        dot += __shfl_xor_sync(0xffffffffu, dot, off);

    if (lane == 0)
        g_rowv[r] = (m + log2f(S)) * LN2F - dot * 2.0f;
}

__global__ void reduce_kernel(float* __restrict__ out) {
    __shared__ float sm[8];
    float s = 0.f;
    for (int i = threadIdx.x; i < TWO_N; i += 256) s += g_rowv[i];
#pragma unroll
    for (int off = 16; off >= 1; off >>= 1)
        s += __shfl_xor_sync(0xffffffffu, s, off);
    if ((threadIdx.x & 31) == 0) sm[threadIdx.x >> 5] = s;
    __syncthreads();
    if (threadIdx.x < 8) {
        s = sm[threadIdx.x];
#pragma unroll
        for (int off = 4; off >= 1; off >>= 1)
            s += __shfl_xor_sync(0x000000ffu, s, off);
        if (threadIdx.x == 0) out[0] = s / (float)TWO_N;
    }
}

extern "C" void kernel_launch(void* const* d_in, const int* in_sizes, int n_in,
                              void* d_out, int out_size) {
    const float* zi = (const float*)d_in[0];
    const float* zj = (const float*)d_in[1];
    float* out = (float*)d_out;

    cudaStreamCaptureStatus st = cudaStreamCaptureStatusNone;
    cudaError_t qe = cudaStreamIsCapturing(0, &st);
    if (qe == cudaSuccess && st == cudaStreamCaptureStatusNone) {
        cudaFuncSetAttribute(tile_kernel,
                             cudaFuncAttributeMaxDynamicSharedMemorySize, DYN_BYTES);
    } else {
        cudaGetLastError();
    }

    convert_kernel<<<(TWO_N * DD / 8 + 255) / 256, 256>>>(zi, zj);
    tile_kernel<<<NBLK, 256, DYN_BYTES>>>();
    finalize_kernel<<<(TWO_N * 32) / 256, 256>>>(zi, zj);
    reduce_kernel<<<1, 256>>>(out);
}

// round 10
// speedup vs baseline: 5.9596x; 1.6537x over previous
#include <cuda_runtime.h>
#include <cuda_bf16.h>
#include <cstdint>

#define NN      4096
#define DD      256
#define TWO_N   8192
#define NTILES  64
#define NBLK    2080        // NTILES*(NTILES+1)/2 upper-tri tiles
#define BMN     128
#define KC      64          // K-chunk (bf16) -> 128B rows, 16B-atom swizzle
#define NCHUNK  4           // DD / KC
#define NSTAGE  3
#define SCALE2  2.8853900817779268f   // (1/T) * log2(e)
#define LN2F    0.6931471805599453f

#define TILE_BYTES 16384                    // 128 rows x 64 bf16 x 2B
#define BUF_BYTES  (2 * TILE_BYTES)         // A, B per stage
#define DYN_BYTES  (NSTAGE * BUF_BYTES + 1024)

// z in bf16, PRE-SWIZZLED tile layout: [64 row-blocks][4 chunks][16KB tile]
// tile byte (row, col): SWZ(row*128 + col*2)
__device__ __nv_bfloat16 g_zt[TWO_N * DD];
// scratch partials (base-2 domain)
__device__ float g_pm[TWO_N * NTILES];
__device__ float g_ps[TWO_N * NTILES];
__device__ float g_rowv[TWO_N];

// ---------------- helpers ----------------
__device__ __forceinline__ uint32_t smem_u32(const void* p) {
    uint32_t a;
    asm("{ .reg .u64 t; cvta.to.shared.u64 t, %1; cvt.u32.u64 %0, t; }" : "=r"(a) : "l"(p));
    return a;
}
#define SWZ(o) ((o) ^ (((o) >> 3) & 0x70))
#define MBAR_INIT(mb, c) asm volatile("mbarrier.init.shared.b64 [%0], %1;" :: "r"((uint32_t)(mb)), "r"((uint32_t)(c)) : "memory")
#define MBAR_EXPECT(mb, n) asm volatile("mbarrier.arrive.expect_tx.shared.b64 _, [%0], %1;" :: "r"((uint32_t)(mb)), "r"((uint32_t)(n)) : "memory")
#define BULK_G2S(dst, src, n, mb) \
    asm volatile("cp.async.bulk.shared::cluster.global.mbarrier::complete_tx::bytes [%0], [%1], %2, [%3];" \
        :: "r"((uint32_t)(dst)), "l"(src), "r"((uint32_t)(n)), "r"((uint32_t)(mb)) : "memory")
#define MBAR_WAIT(mb, ph) do {                                                   \
    uint32_t _m = (uint32_t)(mb), _p = (uint32_t)(ph), _d;                       \
    asm volatile("{\n\t.reg .pred p;\n\t"                                        \
        "mbarrier.try_wait.parity.acquire.cta.shared::cta.b64 p, [%1], %2;\n\t"  \
        "selp.b32 %0, 1, 0, p;\n\t}" : "=r"(_d) : "r"(_m), "r"(_p) : "memory");  \
    if (!_d) {                                                                   \
        asm volatile("{\n\t.reg .pred P1;\n\tWL_%=:\n\t"                         \
            "mbarrier.try_wait.parity.acquire.cta.shared::cta.b64 P1, [%0], %1, 0x989680;\n\t" \
            "@P1 bra.uni WD_%=;\n\tbra.uni WL_%=;\n\tWD_%=:\n\t}"                \
            :: "r"(_m), "r"(_p) : "memory");                                     \
    } } while (0)
#define LDM_X4(r, a) \
    asm volatile("ldmatrix.sync.aligned.m8n8.x4.shared.b16 {%0,%1,%2,%3}, [%4];" \
        : "=r"((r)[0]), "=r"((r)[1]), "=r"((r)[2]), "=r"((r)[3]) : "r"(a))
#define LDM_X2(r, a) \
    asm volatile("ldmatrix.sync.aligned.m8n8.x2.shared.b16 {%0,%1}, [%2];" \
        : "=r"((r)[0]), "=r"((r)[1]) : "r"(a))
#define MMA16816(c, a, b) \
    asm volatile("mma.sync.aligned.m16n8k16.row.col.f32.bf16.bf16.f32 " \
        "{%0,%1,%2,%3}, {%4,%5,%6,%7}, {%8,%9}, {%0,%1,%2,%3};" \
        : "+f"((c)[0]), "+f"((c)[1]), "+f"((c)[2]), "+f"((c)[3]) \
        : "r"((a)[0]), "r"((a)[1]), "r"((a)[2]), "r"((a)[3]), "r"((b)[0]), "r"((b)[1]))

__device__ __forceinline__ const float* zrow(const float* zi, const float* zj, int r) {
    return (r < NN) ? (zi + (long)r * DD) : (zj + (long)(r - NN) * DD);
}

// exp2 on the (otherwise idle) MUFU pipe
__device__ __forceinline__ float ex2a(float u) {
    float r;
    asm("ex2.approx.f32 %0, %1;" : "=f"(r) : "f"(u));
    return r;
}

// ---- pre-pass: round z to bf16 and write PRE-SWIZZLED tile layout ----
__global__ void convert_kernel(const float* __restrict__ zi, const float* __restrict__ zj) {
    const long idx8 = ((long)blockIdx.x * blockDim.x + threadIdx.x) * 8;
    if (idx8 >= (long)TWO_N * DD) return;
    const int r  = (int)(idx8 >> 8);       // DD = 256
    const int d0 = (int)(idx8 & 255);
    const float* src = zrow(zi, zj, r) + d0;
    float4 a = *(const float4*)(src);
    float4 b = *(const float4*)(src + 4);
    __nv_bfloat162 h[4];
    h[0] = __floats2bfloat162_rn(a.x, a.y);
    h[1] = __floats2bfloat162_rn(a.z, a.w);
    h[2] = __floats2bfloat162_rn(b.x, b.y);
    h[3] = __floats2bfloat162_rn(b.z, b.w);

    const int rb   = r >> 7;
    const int row  = r & 127;
    const int ch   = d0 >> 6;              // KC = 64
    const int col0 = d0 & 63;
    char* tile = (char*)g_zt + ((long)(rb * NCHUNK + ch) << 14);
    const uint32_t o = (uint32_t)(row * 128 + col0 * 2);   // multiple of 16
    *(uint4*)(tile + SWZ(o)) = *(uint4*)h;
}

__global__ __launch_bounds__(256, 2)
void tile_kernel() {
    // triangular decode: block t -> (br, bc), bc >= br
    const int t = blockIdx.x;
    const float fN = (float)NTILES + 0.5f;
    int br = (int)(fN - sqrtf(fmaxf(fN * fN - 2.0f * (float)t, 0.0f)));
    if (br > NTILES - 1) br = NTILES - 1;
    if (br < 0) br = 0;
    while ((br + 1) * NTILES - ((br + 1) * br) / 2 <= t) br++;
    while (br * NTILES - (br * (br - 1)) / 2 > t) br--;
    const int bc = br + (t - (br * NTILES - (br * (br - 1)) / 2));

    extern __shared__ char dynsmem[];
    __shared__ float s_row[BMN][4];
    __shared__ float s_col[BMN][2];
    __shared__ float s_red[8];
    __shared__ __align__(8) unsigned long long s_mbar[NSTAGE];

    const int tid  = threadIdx.x;
    const int wid  = tid >> 5;
    const int lane = tid & 31;
    const int wm   = (wid >> 2) * 64;
    const int wn   = (wid & 3) * 32;

    const uint32_t dynbase = (smem_u32(dynsmem) + 1023u) & ~1023u;
    uint32_t mbar[NSTAGE];
#pragma unroll
    for (int s = 0; s < NSTAGE; s++) mbar[s] = smem_u32(&s_mbar[s]);

    const char* Ag = (const char*)g_zt + ((long)(br * NCHUNK) << 14);
    const char* Bg = (const char*)g_zt + ((long)(bc * NCHUNK) << 14);

    if (tid == 0) {
#pragma unroll
        for (int s = 0; s < NSTAGE; s++) MBAR_INIT(mbar[s], 1);
    }
    __syncthreads();

    // prologue: stage chunks 0..2
    if (tid == 0) {
#pragma unroll
        for (int p = 0; p < NSTAGE; p++) {
            const uint32_t buf = dynbase + (uint32_t)p * BUF_BYTES;
            MBAR_EXPECT(mbar[p], BUF_BYTES);
            BULK_G2S(buf,              Ag + ((long)p << 14), TILE_BYTES, mbar[p]);
            BULK_G2S(buf + TILE_BYTES, Bg + ((long)p << 14), TILE_BYTES, mbar[p]);
        }
    }

    // per-lane ldmatrix constants (16B-atom swizzle xor mask constant per lane)
    const int rA  = lane & 15;
    const uint32_t kbA  = (uint32_t)((lane >> 4) * 16);
    const uint32_t xorA = (uint32_t)((rA & 7) << 4);
    const int rB  = lane & 7;
    const uint32_t kbB  = (uint32_t)(((lane >> 3) & 1) * 16);
    const uint32_t xorB = (uint32_t)(rB << 4);
    uint32_t ArowB[4], BrowB[4];
#pragma unroll
    for (int mi = 0; mi < 4; mi++) ArowB[mi] = (uint32_t)((wm + mi * 16 + rA) * 128);
#pragma unroll
    for (int ni = 0; ni < 4; ni++) BrowB[ni] = (uint32_t)((wn + ni * 8 + rB) * 128);

    float acc[4][4][4];
#pragma unroll
    for (int mi = 0; mi < 4; mi++)
#pragma unroll
        for (int ni = 0; ni < 4; ni++)
#pragma unroll
            for (int q = 0; q < 4; q++) acc[mi][ni][q] = 0.f;

    // ---- mainloop: 3-stage bulk-copy pipeline, bf16 k16 steps ----
#pragma unroll 1
    for (int c = 0; c < NCHUNK; c++) {
        const int s = c % NSTAGE;
        const uint32_t buf = dynbase + (uint32_t)s * BUF_BYTES;
        MBAR_WAIT(mbar[s], (c / NSTAGE) & 1);

        const uint32_t At = buf;
        const uint32_t Bt = buf + TILE_BYTES;
#pragma unroll
        for (int ks = 0; ks < 4; ks++) {     // k = 16 bf16 per step = 32B
            const uint32_t kA = ((uint32_t)(ks * 32) + kbA) ^ xorA;
            const uint32_t kB = ((uint32_t)(ks * 32) + kbB) ^ xorB;
            uint32_t af[4][4], bf[4][2];
#pragma unroll
            for (int mi = 0; mi < 4; mi++) LDM_X4(af[mi], At + ArowB[mi] + kA);
#pragma unroll
            for (int ni = 0; ni < 4; ni++) LDM_X2(bf[ni], Bt + BrowB[ni] + kB);
#pragma unroll
            for (int mi = 0; mi < 4; mi++)
#pragma unroll
                for (int ni = 0; ni < 4; ni++)
                    MMA16816(acc[mi][ni], af[mi], bf[ni]);
        }
        __syncthreads();   // all warps done reading stage s
        if (c + NSTAGE < NCHUNK && tid == 0) {
            MBAR_EXPECT(mbar[s], BUF_BYTES);
            BULK_G2S(buf,              Ag + ((long)(c + NSTAGE) << 14), TILE_BYTES, mbar[s]);
            BULK_G2S(buf + TILE_BYTES, Bg + ((long)(c + NSTAGE) << 14), TILE_BYTES, mbar[s]);
        }
    }

    // ---- epilogue ----
    const bool isdiag = (br == bc);
    const int lr = lane >> 2;
    const int lc = (lane & 3) * 2;

    float m = -3.0e30f;
#pragma unroll
    for (int mi = 0; mi < 4; mi++)
#pragma unroll
        for (int ni = 0; ni < 4; ni++)
#pragma unroll
            for (int q = 0; q < 4; q++) {
                float x = acc[mi][ni][q] * SCALE2;
                if (isdiag) {
                    const int rloc = wm + mi * 16 + lr + ((q >> 1) << 3);
                    const int cloc = wn + ni * 8 + lc + (q & 1);
                    if (rloc == cloc) x = -3.0e30f;
                }
                acc[mi][ni][q] = x;
                m = fmaxf(m, x);
            }
#pragma unroll
    for (int off = 16; off >= 1; off >>= 1)
        m = fmaxf(m, __shfl_xor_sync(0xffffffffu, m, off));
    if (lane == 0) s_red[wid] = m;
    __syncthreads();
    float Mt = s_red[0];
#pragma unroll
    for (int w = 1; w < 8; w++) Mt = fmaxf(Mt, s_red[w]);

    float rs[4][2], cs[4][2];
#pragma unroll
    for (int i = 0; i < 4; i++) { rs[i][0] = rs[i][1] = 0.f; cs[i][0] = cs[i][1] = 0.f; }
#pragma unroll
    for (int mi = 0; mi < 4; mi++)
#pragma unroll
        for (int ni = 0; ni < 4; ni++) {
            float e0 = ex2a(acc[mi][ni][0] - Mt);
            float e1 = ex2a(acc[mi][ni][1] - Mt);
            float e2 = ex2a(acc[mi][ni][2] - Mt);
            float e3 = ex2a(acc[mi][ni][3] - Mt);
            rs[mi][0] += e0 + e1;  rs[mi][1] += e2 + e3;
            cs[ni][0] += e0 + e2;  cs[ni][1] += e1 + e3;
        }
#pragma unroll
    for (int off = 1; off <= 2; off <<= 1)
#pragma unroll
        for (int mi = 0; mi < 4; mi++)
#pragma unroll
            for (int h = 0; h < 2; h++)
                rs[mi][h] += __shfl_xor_sync(0xffffffffu, rs[mi][h], off);
#pragma unroll
    for (int off = 4; off <= 16; off <<= 1)
#pragma unroll
        for (int ni = 0; ni < 4; ni++)
#pragma unroll
            for (int p = 0; p < 2; p++)
                cs[ni][p] += __shfl_xor_sync(0xffffffffu, cs[ni][p], off);

    if ((lane & 3) == 0) {
#pragma unroll
        for (int mi = 0; mi < 4; mi++)
#pragma unroll
            for (int h = 0; h < 2; h++)
                s_row[wm + mi * 16 + lr + 8 * h][wid & 3] = rs[mi][h];
    }
    if (lane < 4) {
#pragma unroll
        for (int ni = 0; ni < 4; ni++)
#pragma unroll
            for (int p = 0; p < 2; p++)
                s_col[wn + ni * 8 + 2 * lane + p][wid >> 2] = cs[ni][p];
    }
    __syncthreads();

    if (tid < BMN) {
        const float rsum = s_row[tid][0] + s_row[tid][1] + s_row[tid][2] + s_row[tid][3];
        const int gr = br * BMN + tid;
        g_pm[gr * NTILES + bc] = Mt;
        g_ps[gr * NTILES + bc] = rsum;
    } else if (!isdiag) {
        const int cc = tid - BMN;
        const float csum = s_col[cc][0] + s_col[cc][1];
        const int gc = bc * BMN + cc;
        g_pm[gc * NTILES + br] = Mt;
        g_ps[gc * NTILES + br] = csum;
    }
}

// One warp per row: merge 64 (m2, s) partials -> lse; positive dot (fp32).
__global__ void finalize_kernel(const float* __restrict__ zi, const float* __restrict__ zj) {
    const int warp = (blockIdx.x * blockDim.x + threadIdx.x) >> 5;
    const int lane = threadIdx.x & 31;
    if (warp >= TWO_N) return;
    const int r = warp;

    const float m0 = g_pm[r * NTILES + lane];
    const float m1 = g_pm[r * NTILES + 32 + lane];
    const float s0 = g_ps[r * NTILES + lane];
    const float s1 = g_ps[r * NTILES + 32 + lane];
    float m = fmaxf(m0, m1);
#pragma unroll
    for (int off = 16; off >= 1; off >>= 1)
        m = fmaxf(m, __shfl_xor_sync(0xffffffffu, m, off));
    float S = s0 * ex2a(m0 - m) + s1 * ex2a(m1 - m);
#pragma unroll
    for (int off = 16; off >= 1; off >>= 1)
        S += __shfl_xor_sync(0xffffffffu, S, off);

    const int p = (r < NN) ? r + NN : r - NN;
    const float* a = zrow(zi, zj, r);
    const float* b = zrow(zi, zj, p);
    float dot = 0.f;
#pragma unroll
    for (int q = 0; q < 2; q++) {
        const int k = lane * 8 + q * 4;
        float4 x = *(const float4*)(a + k);
        float4 y = *(const float4*)(b + k);
        dot += x.x * y.x + x.y * y.y + x.z * y.z + x.w * y.w;
    }
#pragma unroll
    for (int off = 16; off >= 1; off >>= 1)
        dot += __shfl_xor_sync(0xffffffffu, dot, off);

    if (lane == 0)
        g_rowv[r] = (m + log2f(S)) * LN2F - dot * 2.0f;
}

__global__ void reduce_kernel(float* __restrict__ out) {
    __shared__ float sm[32];
    const int tid = threadIdx.x;          // 1024 threads
    float4 x = *(const float4*)(g_rowv + tid * 8);
    float4 y = *(const float4*)(g_rowv + tid * 8 + 4);
    float s = (x.x + x.y) + (x.z + x.w) + (y.x + y.y) + (y.z + y.w);
#pragma unroll
    for (int off = 16; off >= 1; off >>= 1)
        s += __shfl_xor_sync(0xffffffffu, s, off);
    if ((tid & 31) == 0) sm[tid >> 5] = s;
    __syncthreads();
    if (tid < 32) {
        s = sm[tid];
#pragma unroll
        for (int off = 16; off >= 1; off >>= 1)
            s += __shfl_xor_sync(0xffffffffu, s, off);
        if (tid == 0) out[0] = s / (float)TWO_N;
    }
}

extern "C" void kernel_launch(void* const* d_in, const int* in_sizes, int n_in,
                              void* d_out, int out_size) {
    const float* zi = (const float*)d_in[0];
    const float* zj = (const float*)d_in[1];
    float* out = (float*)d_out;

    cudaStreamCaptureStatus st = cudaStreamCaptureStatusNone;
    cudaError_t qe = cudaStreamIsCapturing(0, &st);
    if (qe == cudaSuccess && st == cudaStreamCaptureStatusNone) {
        cudaFuncSetAttribute(tile_kernel,
                             cudaFuncAttributeMaxDynamicSharedMemorySize, DYN_BYTES);
    } else {
        cudaGetLastError();
    }

    convert_kernel<<<(TWO_N * DD / 8 + 255) / 256, 256>>>(zi, zj);
    tile_kernel<<<NBLK, 256, DYN_BYTES>>>();
    finalize_kernel<<<(TWO_N * 32) / 256, 256>>>(zi, zj);
    reduce_kernel<<<1, 1024>>>(out);
}